// round 5
// baseline (speedup 1.0000x reference)
#include <cuda_runtime.h>

// QuantumEvolution: B=512 x M=2048. SU(2) step propagators as unit quaternions;
// per-trajectory prefix product. TPB=512 (4 steps/thread) to double occupancy.
// Two-level shuffle scan; L[4] kept in regs; coalesced gmem via padded smem.

#define TPB    512
#define STEPS  4
#define MSTEPS 2048
#define BREAL  512

// smem union buffer (time-disjoint):
//   phase 1: pulses rows [0, 512*9) + noise rows [512*9, 512*9+512*5) = 7168 fl
//   phase 2: output stage rows, 512 * 26 = 13312 floats (52 KB)
#define SM_P_OFF  0
#define SM_N_OFF  (512 * 9)
#define SM_FLOATS (512 * 26)

__device__ __forceinline__ float4 qmul(float4 a, float4 b) {
    // Hamilton product a*b; quaternion (w,x,y,z) in (x,y,z,w) fields.
    float4 r;
    r.x = a.x * b.x - a.y * b.y - a.z * b.z - a.w * b.w;
    r.y = a.x * b.y + a.y * b.x + a.z * b.w - a.w * b.z;
    r.z = a.x * b.z - a.y * b.w + a.z * b.x + a.w * b.y;
    r.w = a.x * b.w + a.y * b.z - a.z * b.y + a.w * b.x;
    return r;
}

__device__ __forceinline__ float4 shfl_up_q(float4 v, int off) {
    float4 r;
    r.x = __shfl_up_sync(0xFFFFFFFFu, v.x, off);
    r.y = __shfl_up_sync(0xFFFFFFFFu, v.y, off);
    r.z = __shfl_up_sync(0xFFFFFFFFu, v.z, off);
    r.w = __shfl_up_sync(0xFFFFFFFFu, v.w, off);
    return r;
}

__device__ __forceinline__ float4 stepq(float hx, float hy, float hz) {
    const float dt = 1.0f / 2048.0f;
    float t2 = (dt * dt) * (hx * hx + hy * hy + hz * hz);   // theta^2 <= ~1.5e-5
    float c = 1.f - t2 * (0.5f - t2 * (1.f / 24.f));        // cos(theta)
    float k = dt * (1.f - t2 * ((1.f / 6.f) - t2 * (1.f / 120.f)));  // dt*sinc
    return make_float4(c, k * hx, k * hy, k * hz);
}

__global__ __launch_bounds__(TPB, 3)
void qe_kernel(const float* __restrict__ noise,
               const float* __restrict__ pulses,
               float* __restrict__ out) {
    __shared__ float  sm[SM_FLOATS];
    __shared__ float4 wtot[TPB / 32];
    __shared__ float4 wscan[TPB / 32];

    const int tid  = threadIdx.x;
    const int lane = tid & 31;
    const int wid  = tid >> 5;
    const int b    = blockIdx.x;

    // ---- Phase 1: coalesced load -> padded smem rows ----
    // pulses: 4096 floats = 1024 f4; thread gets f4 g = tid + 512k (k<2).
    const float4* gp = reinterpret_cast<const float4*>(pulses + (size_t)b * MSTEPS * 2);
#pragma unroll
    for (int k = 0; k < 2; k++) {
        int g = tid + TPB * k;
        float4 v = gp[g];
        int row = g >> 1, col = (g & 1) * 4;        // row pad 9 (odd -> no conflicts)
        float* d = &sm[SM_P_OFF + row * 9 + col];
        d[0] = v.x; d[1] = v.y; d[2] = v.z; d[3] = v.w;
    }
    // noise: 2048 floats = 512 f4; thread tid's 4 noise floats = exactly one f4.
    {
        const float4* gn = reinterpret_cast<const float4*>(noise + (size_t)b * MSTEPS);
        float4 v = gn[tid];
        float* d = &sm[SM_N_OFF + tid * 5];          // row pad 5
        d[0] = v.x; d[1] = v.y; d[2] = v.z; d[3] = v.w;
    }
    __syncthreads();

    // ---- Chunk: 4 steps, keep local inclusive prefixes L[i] in regs ----
    float4 L[STEPS];
    {
        const float* pr = &sm[SM_P_OFF + tid * 9];
        const float* nr = &sm[SM_N_OFF + tid * 5];
        float4 q = stepq(pr[0], pr[1], 0.5f + nr[0]);
        L[0] = q;
#pragma unroll
        for (int i = 1; i < STEPS; i++) {
            q = qmul(stepq(pr[2 * i], pr[2 * i + 1], 0.5f + nr[i]), q);
            L[i] = q;
        }
    }

    // ---- Warp-level inclusive scan of chunk products ----
    float4 v = L[STEPS - 1];
#pragma unroll
    for (int off = 1; off < 32; off <<= 1) {
        float4 o = shfl_up_q(v, off);
        if (lane >= off) v = qmul(v, o);
    }
    if (lane == 31) wtot[wid] = v;
    __syncthreads();

    // ---- Second level: warp 0 scans the 16 warp totals via shuffles ----
    if (wid == 0) {
        float4 t = (lane < 16) ? wtot[lane] : make_float4(1.f, 0.f, 0.f, 0.f);
#pragma unroll
        for (int off = 1; off < 16; off <<= 1) {
            float4 o = shfl_up_q(t, off);
            if (lane >= off) t = qmul(t, o);
        }
        if (lane < 16) wscan[lane] = t;
    }
    __syncthreads();

    // Exclusive prefix for this thread's chunk.
    float4 WE = (wid > 0) ? wscan[wid - 1] : make_float4(1.f, 0.f, 0.f, 0.f);
    float4 TE = shfl_up_q(v, 1);
    if (lane == 0) TE = make_float4(1.f, 0.f, 0.f, 0.f);
    const float4 E = qmul(TE, WE);

    // ---- Phase 2: epilogue into stage smem (aliases input region) ----
    // Row t: 24 output floats, pad 26 (13 f2-units, odd -> conflict-free .64).
#pragma unroll
    for (int i = 0; i < STEPS; i++) {
        float4 P = qmul(L[i], E);                    // independent per step
        float w = P.x, x = P.y, y = P.z, z = P.w;
        float xz = x * z, wy = w * y, yz = y * z, wx = w * x;
        float xy = x * y, wz = w * z, xx = x * x, yy = y * y, zz = z * z;
        float2* d2 = reinterpret_cast<float2*>(&sm[tid * 26 + i * 6]);
        d2[0] = make_float2(2.f * (xz + wy), 2.f * (yz - wx));      // r0:sx,sy
        d2[1] = make_float2(1.f - 2.f * (xx + yy), 1.f - 2.f * (yy + zz)); // r0:sz r1:sx
        d2[2] = make_float2(2.f * (xy + wz), 2.f * (xz - wy));      // r1:sy,sz
    }
    __syncthreads();

    // ---- Coalesced copy-out: 3072 f4 per block = 6 f4/thread ----
    float4* og = reinterpret_cast<float4*>(out + (size_t)b * (MSTEPS * 6));
#pragma unroll
    for (int k = 0; k < 6; k++) {
        int g4 = tid + TPB * k;
        int r  = g4 / 6;                              // stage row
        int c2 = 2 * (g4 - r * 6);                    // f2 index within row
        const float2* s2 = reinterpret_cast<const float2*>(&sm[r * 26]) + c2;
        float2 a = s2[0], bb = s2[1];
        og[g4] = make_float4(a.x, a.y, bb.x, bb.y);
    }
}

extern "C" void kernel_launch(void* const* d_in, const int* in_sizes, int n_in,
                              void* d_out, int out_size) {
    const float* noise  = (const float*)d_in[0];   // [512, 2048, 1]
    const float* pulses = (const float*)d_in[1];   // [512, 2048, 2]
    if (in_sizes[0] > in_sizes[1]) {               // defensive: order by size
        const float* t = noise; noise = pulses; pulses = t;
    }
    qe_kernel<<<BREAL, TPB>>>(noise, pulses, (float*)d_out);
}